// round 15
// baseline (speedup 1.0000x reference)
#include <cuda_runtime.h>
#include <math.h>

#define COL 14
#define NJ 14
#define NPIX 196
#define NB 8192
#define NJOINT (NB * NJ)                   // 114688
#define THREADS 256
#define NWARPS 8
#define GRID 760                           // 152 SMs x 5 CTAs
#define WTOT (GRID * NWARPS)               // 6080 warps
#define NPAIRS (NJOINT / 2)                // 57344 pairs of joints
#define PEXTRA (NPAIRS - 9 * WTOT)         // 2624 warps get 10 pairs, rest 9
#define SLOTS 3

struct GParams {
    float  GT[NPIX];     // GT[c*14+r] = G[r][c]
    float4 lut[NPIX];    // (m2inv, m2nmi, T2, 0) per (yi,xi) cell
};

__device__ float    g_d1[GRID];
__device__ float    g_d2[GRID];
__device__ float    g_cnt[GRID];
__device__ unsigned g_ticket;   // zero-init at load; net-zero per run

// ---- packed f32x2 helpers ----
__device__ __forceinline__ unsigned long long pack2(float lo, float hi) {
    unsigned long long r;
    asm("mov.b64 %0,{%1,%2};" : "=l"(r) : "f"(lo), "f"(hi));
    return r;
}
__device__ __forceinline__ void unpack2(unsigned long long p, float& lo, float& hi) {
    asm("mov.b64 {%0,%1},%2;" : "=f"(lo), "=f"(hi) : "l"(p));
}
__device__ __forceinline__ unsigned long long mul2(unsigned long long a, unsigned long long b) {
    unsigned long long r;
    asm("mul.rn.f32x2 %0,%1,%2;" : "=l"(r) : "l"(a), "l"(b));
    return r;
}
__device__ __forceinline__ unsigned long long add2(unsigned long long a, unsigned long long b) {
    unsigned long long r;
    asm("add.rn.f32x2 %0,%1,%2;" : "=l"(r) : "l"(a), "l"(b));
    return r;
}
__device__ __forceinline__ unsigned long long fma2(unsigned long long a, unsigned long long b,
                                                   unsigned long long c) {
    unsigned long long r;
    asm("fma.rn.f32x2 %0,%1,%2,%3;" : "=l"(r) : "l"(a), "l"(b), "l"(c));
    return r;
}

#define CP_ASYNC16(dst_u32, src_ptr) \
    asm volatile("cp.async.cg.shared.global [%0], [%1], 16;" \
                 :: "r"(dst_u32), "l"(src_ptr) : "memory")
#define CP_COMMIT() asm volatile("cp.async.commit_group;" ::: "memory")
#define CP_WAIT(n)  asm volatile("cp.async.wait_group %0;" :: "n"(n) : "memory")

__global__ __launch_bounds__(THREADS, 5) void main_kernel(
    const float* __restrict__ outp,
    const float* __restrict__ t,
    const float* __restrict__ v,
    float* __restrict__ o,
    const GParams gp)
{
    __shared__ __align__(16) float sH[NWARPS * SLOTS * 2 * NPIX];   // 37632 B
    __shared__ __align__(16) float sGT[NPIX];
    __shared__ float sred[NWARPS][3];
    __shared__ int   sBidx[NWARPS][32];
    __shared__ int   s_last;
    __shared__ double dra[NWARPS], drb[NWARPS], drc[NWARPS];

    const int tid = threadIdx.x;
    if (tid < NPIX) sGT[tid] = gp.GT[tid];
    __syncthreads();

    const int lane = tid & 31;
    const int warp = tid >> 5;
    const int gwarp = blockIdx.x * NWARPS + warp;
    const bool hasB = lane < 17;
    const int base4 = 4 * lane;
    const int baseByte = 16 * lane;

    // contiguous pair-run per warp: 10-pair warps first, then 9-pair
    const int np = (gwarp < PEXTRA) ? 10 : 9;
    const int p0 = gwarp * 9 + min(gwarp, PEXTRA);
    const int joint_start = 2 * p0;
    const int ng = np;                      // groups of 2 consecutive joints

    const unsigned sHbase =
        (unsigned)__cvta_generic_to_shared(&sH[warp * (SLOTS * 2 * NPIX)]);
    const float* sHw = &sH[warp * (SLOTS * 2 * NPIX)];

    // ---- per-lane pair geometry ----
    int ybO[4], xbO[4];
    {
        #pragma unroll
        for (int p = 0; p < 4; ++p) {
            int e0 = (p < 2) ? (base4 + 2 * p) : (128 + base4 + 2 * (p - 2));
            if (p >= 2 && !hasB) e0 = 0;
            int y = e0 / COL;
            ybO[p] = y * 4;
            xbO[p] = (e0 - y * COL) * 4;
        }
    }

    // ---- issue cursor: one division per warp, then incremental ----
    int ij;                                  // j-index of next group's first joint
    const float* hp;                         // heatmap ptr of next group's first joint
    {
        const int b0 = joint_start / NJ;
        ij = joint_start - b0 * NJ;
        hp = outp + ((size_t)b0 * (3 * NJ) + ij) * NPIX;
    }

    auto issue = [&](int slot) {
        const float* s0 = hp;
        const float* s1 = hp + NPIX + ((ij == 13) ? 28 * NPIX : 0);
        {
            const unsigned dst = sHbase + (slot * 2) * (NPIX * 4);
            CP_ASYNC16(dst + baseByte, (const char*)s0 + baseByte);
            if (hasB) CP_ASYNC16(dst + 512 + baseByte, (const char*)s0 + 512 + baseByte);
        }
        {
            const unsigned dst = sHbase + (slot * 2 + 1) * (NPIX * 4);
            CP_ASYNC16(dst + baseByte, (const char*)s1 + baseByte);
            if (hasB) CP_ASYNC16(dst + 512 + baseByte, (const char*)s1 + 512 + baseByte);
        }
        CP_COMMIT();
        hp += 2 * NPIX + ((ij >= 12) ? 28 * NPIX : 0);
        ij += 2; if (ij >= NJ) ij -= NJ;
    };

    float d1 = 0.0f;
    int jc = joint_start;                    // compute cursor (joint index)

    auto compute = [&](int g, int slot) {
        const float4 tv = *reinterpret_cast<const float4*>(t + 2 * (size_t)jc);
        const float4 vv = *reinterpret_cast<const float4*>(v + 2 * (size_t)jc);
        jc += 2;
        #pragma unroll
        for (int i = 0; i < 2; ++i) {
            const float* sj = sHw + (slot * 2 + i) * NPIX;
            const float4 a = *reinterpret_cast<const float4*>(sj + base4);
            float4 b = make_float4(0.0f, 0.0f, 0.0f, 0.0f);
            if (hasB) b = *reinterpret_cast<const float4*>(sj + 128 + base4);

            const unsigned long long p01 = pack2(a.x, a.y);
            const unsigned long long p23 = pack2(a.z, a.w);
            const unsigned long long p45 = pack2(b.x, b.y);
            const unsigned long long p67 = pack2(b.z, b.w);

            unsigned long long s2 = fma2(p01, p01, mul2(p23, p23));
            s2 = fma2(p45, p45, s2);
            s2 = fma2(p67, p67, s2);
            float h2lo, h2hi; unpack2(s2, h2lo, h2hi);
            const float ph2 = h2lo + h2hi;

            const float t0 = i ? tv.z : tv.x;
            const float t1 = i ? tv.w : tv.y;
            const float v0 = i ? vv.z : vv.x;
            const int xi = (int)(t0 * 14.0f);
            const int yi = (int)(t1 * 14.0f);
            const bool inb = (xi >= 0) && (xi <= COL - 1) && (yi >= 0) && (yi <= COL - 1);
            const bool vis = ((int)v0) == 1;
            const bool scat = vis && inb;       // warp-uniform

            if (scat) {
                unsigned long long sh = add2(add2(p01, p23), add2(p45, p67));
                float shlo, shhi; unpack2(sh, shlo, shhi);
                const float ph = shlo + shhi;

                const char* gyrowB = reinterpret_cast<const char*>(sGT + yi * COL);
                const char* gxrowB = reinterpret_cast<const char*>(sGT + xi * COL);
                unsigned long long acc = 0ull;
                {
                    const float gy = *(const float*)(gyrowB + ybO[0]);
                    const unsigned long long gx2 = *(const unsigned long long*)(gxrowB + xbO[0]);
                    acc = fma2(mul2(gx2, p01), pack2(gy, gy), acc);
                }
                {
                    const float gy = *(const float*)(gyrowB + ybO[1]);
                    const unsigned long long gx2 = *(const unsigned long long*)(gxrowB + xbO[1]);
                    acc = fma2(mul2(gx2, p23), pack2(gy, gy), acc);
                }
                {
                    const float gy = *(const float*)(gyrowB + ybO[2]);
                    const unsigned long long gx2 = *(const unsigned long long*)(gxrowB + xbO[2]);
                    acc = fma2(mul2(gx2, p45), pack2(gy, gy), acc);
                }
                {
                    const float gy = *(const float*)(gyrowB + ybO[3]);
                    const unsigned long long gx2 = *(const unsigned long long*)(gxrowB + xbO[3]);
                    acc = fma2(mul2(gx2, p67), pack2(gy, gy), acc);
                }
                float htlo, hthi; unpack2(acc, htlo, hthi);
                const float phtt = htlo + hthi;

                const float4 lut = gp.lut[yi * COL + xi];   // single LDC.128

                d1 += fmaf(lut.x, phtt, fmaf(lut.y, ph, ph2));
                if (lane == 0) d1 += lut.z;

                float best = fmaxf(fmaxf(a.x, a.y), fmaxf(a.z, a.w));
                if (hasB) best = fmaxf(best, fmaxf(fmaxf(b.x, b.y), fmaxf(b.z, b.w)));
                int idx = 0x7fffffff;
                if (hasB) {
                    idx = (b.w == best) ? (131 + base4) : idx;
                    idx = (b.z == best) ? (130 + base4) : idx;
                    idx = (b.y == best) ? (129 + base4) : idx;
                    idx = (b.x == best) ? (128 + base4) : idx;
                }
                idx = (a.w == best) ? (3 + base4) : idx;
                idx = (a.z == best) ? (2 + base4) : idx;
                idx = (a.y == best) ? (1 + base4) : idx;
                idx = (a.x == best) ? (base4) : idx;

                unsigned u = __float_as_uint(best);
                unsigned mono = ((int)u < 0) ? ~u : (u | 0x80000000u);
                unsigned mmax = __reduce_max_sync(0xffffffffu, mono);
                int cand = (mono == mmax) ? idx : 0x7fffffff;
                int bidx = __reduce_min_sync(0xffffffffu, cand);
                if (lane == 0) sBidx[warp][2 * g + i] = bidx;
            } else {
                float pr = 0.0f;
                if (lane < 4) {
                    pr = fmaf(a.x, a.x, a.y * a.y);
                    if (lane < 3) pr += fmaf(a.z, a.z, a.w * a.w);
                }
                d1 += ph2 - pr;
            }
        }
    };

    // ---- continuous 3-slot pipeline over ng groups (ng >= 9) ----
    issue(0); issue(1); issue(2);
    {
        int slot = 0;
        for (int g = 0; g < ng - 3; ++g) {
            CP_WAIT(2);
            compute(g, slot);
            issue(slot);
            slot = (slot == 2) ? 0 : slot + 1;
        }
        CP_WAIT(2); compute(ng - 3, slot); slot = (slot == 2) ? 0 : slot + 1;
        CP_WAIT(1); compute(ng - 2, slot); slot = (slot == 2) ? 0 : slot + 1;
        CP_WAIT(0); compute(ng - 1, slot);
    }

    // warp-reduce d1
    #pragma unroll
    for (int off = 16; off; off >>= 1)
        d1 += __shfl_xor_sync(0xffffffffu, d1, off);

    __syncwarp();

    // ---- phase B: one joint per lane (up to 20, consecutive) ----
    float d2 = 0.0f, cntf = 0.0f;
    if (lane < 2 * np) {
        const int joint = joint_start + lane;
        const float t0 = t[2 * joint];
        const float t1 = t[2 * joint + 1];
        const float v0 = v[2 * joint];
        const int xi = (int)(t0 * 14.0f);
        const int yi = (int)(t1 * 14.0f);
        const bool inb = (xi >= 0) && (xi <= COL - 1) && (yi >= 0) && (yi <= COL - 1);
        const bool vis = ((int)v0) == 1;
        const float vef = (vis && !inb) ? 0.0f : v0;
        const float veI = (((int)vef) == 1) ? 1.0f : 0.0f;
        cntf = veI;

        if (vis && inb) {
            const int b2 = joint / NJ;
            const int j2 = joint - b2 * NJ;
            const int bidx = sBidx[warp][lane];
            const size_t ob = (size_t)b2 * (3 * NJ) * NPIX;
            const float ox = outp[ob + (size_t)(NJ + j2) * NPIX + bidx];
            const float oy = outp[ob + (size_t)(2 * NJ + j2) * NPIX + bidx];
            const int yc = bidx / COL;
            const int xc = bidx - yc * COL;
            const float px = (ox + (float)xc) * (1.0f / 14.0f);
            const float py = (oy + (float)yc) * (1.0f / 14.0f);
            const float dx = (px - t0) * vef;
            const float dy = (py - t1) * vef;
            d2 = fmaf(dx, dx, dy * dy);
        }
    }
    #pragma unroll
    for (int off = 16; off; off >>= 1) {
        d2   += __shfl_xor_sync(0xffffffffu, d2, off);
        cntf += __shfl_xor_sync(0xffffffffu, cntf, off);
    }

    if (lane == 0) { sred[warp][0] = d1; sred[warp][1] = d2; sred[warp][2] = cntf; }
    __syncthreads();

    if (tid == 0) {
        float a = 0.0f, bsum = 0.0f, c = 0.0f;
        #pragma unroll
        for (int w = 0; w < NWARPS; ++w) { a += sred[w][0]; bsum += sred[w][1]; c += sred[w][2]; }
        g_d1[blockIdx.x] = a;
        g_d2[blockIdx.x] = bsum;
        g_cnt[blockIdx.x] = c;
        __threadfence();
        unsigned old = atomicAdd(&g_ticket, 1u);
        s_last = (old == GRID - 1);
    }
    __syncthreads();

    // ---- last block: grid reduction ----
    if (s_last) {
        if (tid == 0) g_ticket = 0;          // net-zero per run
        __threadfence();
        double a = 0.0, bsum = 0.0, c = 0.0;
        for (int i = tid; i < GRID; i += THREADS) {
            a    += (double)g_d1[i];
            bsum += (double)g_d2[i];
            c    += (double)g_cnt[i];
        }
        #pragma unroll
        for (int off = 16; off; off >>= 1) {
            a    += __shfl_xor_sync(0xffffffffu, a, off);
            bsum += __shfl_xor_sync(0xffffffffu, bsum, off);
            c    += __shfl_xor_sync(0xffffffffu, c, off);
        }
        if (lane == 0) { dra[warp] = a; drb[warp] = bsum; drc[warp] = c; }
        __syncthreads();
        if (tid == 0) {
            double A = 0.0, B = 0.0, C = 0.0;
            #pragma unroll
            for (int w = 0; w < NWARPS; ++w) { A += dra[w]; B += drb[w]; C += drc[w]; }
            o[0] = (float)(A / C + B / C);   // n2 == cnt (v is a tiled 0/1 mask)
        }
    }
}

extern "C" void kernel_launch(void* const* d_in, const int* in_sizes, int n_in,
                              void* d_out, int out_size)
{
    const float* outp = (const float*)d_in[0];
    const float* t    = (const float*)d_in[1];
    const float* v    = (const float*)d_in[2];

    GParams gp;
    {
        double w[9], ws = 0.0;
        for (int k = 0; k < 9; ++k) { w[k] = exp(-0.5 * (double)((k - 4) * (k - 4))); ws += w[k]; }
        for (int k = 0; k < 9; ++k) w[k] /= ws;
        for (int r = 0; r < COL; ++r)
            for (int c = 0; c < COL; ++c) {
                double s = 0.0;
                for (int k = 0; k < 9; ++k) {
                    int rr = r + k;   // padded row, pad=4, 'symmetric'
                    int m = (rr < 4) ? (3 - rr) : ((rr > 17) ? (31 - rr) : (rr - 4));
                    if (m == c) s += w[k];
                }
                gp.GT[c * COL + r] = (float)s;
            }
        float cmin[COL], cmax[COL];
        for (int c = 0; c < COL; ++c) {
            float mn = 1e30f, mx = -1e30f;
            for (int r = 0; r < COL; ++r) {
                float gv = gp.GT[c * COL + r];
                mn = fminf(mn, gv);
                mx = fmaxf(mx, gv);
            }
            cmin[c] = mn;
            cmax[c] = mx;
        }
        for (int yic = 0; yic < COL; ++yic)
            for (int xic = 0; xic < COL; ++xic) {
                float mn = cmin[yic] * cmin[xic];
                float mx = cmax[yic] * cmax[xic];
                double invd = 1.0 / ((double)mx - (double)mn);
                float inv = (float)invd;
                double s = 0.0;
                for (int y = 0; y < COL; ++y)
                    for (int x = 0; x < COL; ++x) {
                        float tt = gp.GT[yic * COL + y] * gp.GT[xic * COL + x];
                        float ttn = (tt - mn) * inv;
                        s += (double)ttn * (double)ttn;
                    }
                const int cell = yic * COL + xic;
                gp.lut[cell].x = -2.0f * inv;              // m2inv
                gp.lut[cell].y = -2.0f * (-mn * inv);      // m2nmi
                gp.lut[cell].z = (float)s;                 // T2
                gp.lut[cell].w = 0.0f;
            }
    }

    main_kernel<<<GRID, THREADS>>>(outp, t, v, (float*)d_out, gp);
}

// round 17
// speedup vs baseline: 1.5272x; 1.5272x over previous
#include <cuda_runtime.h>
#include <math.h>

#define COL 14
#define NJ 14
#define NPIX 196
#define NB 8192
#define NJOINT (NB * NJ)                   // 114688
#define THREADS 256
#define NWARPS 8
#define GRID 608                           // 152 SMs x 4 CTAs resident (5th partial)
#define WTOT (GRID * NWARPS)               // 4864 warps
#define NTASKS (NJOINT / 8)                // 14336 tasks of 8 joints
#define SLOTS 3

struct GParams {
    float  GT[NPIX];     // GT[c*14+r] = G[r][c]
    float4 lut[NPIX];    // (m2inv, m2nmi, T2, 0) per (yi,xi) cell
};

__device__ float    g_d1[GRID];
__device__ float    g_d2[GRID];
__device__ float    g_cnt[GRID];
__device__ unsigned g_ticket;   // zero-init at load; net-zero per run

// ---- packed f32x2 helpers ----
__device__ __forceinline__ unsigned long long pack2(float lo, float hi) {
    unsigned long long r;
    asm("mov.b64 %0,{%1,%2};" : "=l"(r) : "f"(lo), "f"(hi));
    return r;
}
__device__ __forceinline__ void unpack2(unsigned long long p, float& lo, float& hi) {
    asm("mov.b64 {%0,%1},%2;" : "=f"(lo), "=f"(hi) : "l"(p));
}
__device__ __forceinline__ unsigned long long mul2(unsigned long long a, unsigned long long b) {
    unsigned long long r;
    asm("mul.rn.f32x2 %0,%1,%2;" : "=l"(r) : "l"(a), "l"(b));
    return r;
}
__device__ __forceinline__ unsigned long long add2(unsigned long long a, unsigned long long b) {
    unsigned long long r;
    asm("add.rn.f32x2 %0,%1,%2;" : "=l"(r) : "l"(a), "l"(b));
    return r;
}
__device__ __forceinline__ unsigned long long fma2(unsigned long long a, unsigned long long b,
                                                   unsigned long long c) {
    unsigned long long r;
    asm("fma.rn.f32x2 %0,%1,%2,%3;" : "=l"(r) : "l"(a), "l"(b), "l"(c));
    return r;
}

#define CP_ASYNC16(dst_u32, src_ptr) \
    asm volatile("cp.async.cg.shared.global [%0], [%1], 16;" \
                 :: "r"(dst_u32), "l"(src_ptr) : "memory")
#define CP_COMMIT() asm volatile("cp.async.commit_group;" ::: "memory")
#define CP_WAIT(n)  asm volatile("cp.async.wait_group %0;" :: "n"(n) : "memory")

__global__ __launch_bounds__(THREADS, 5) void main_kernel(
    const float* __restrict__ outp,
    const float* __restrict__ t,
    const float* __restrict__ v,
    float* __restrict__ o,
    const GParams gp)
{
    __shared__ __align__(16) float sH[NWARPS * SLOTS * 2 * NPIX];   // 37632 B
    __shared__ __align__(16) float sGT[NPIX];
    __shared__ float sred[NWARPS][3];
    __shared__ int   sBidx[NWARPS][32];
    __shared__ int   s_last;
    __shared__ double dra[NWARPS], drb[NWARPS], drc[NWARPS];

    const int tid = threadIdx.x;
    if (tid < NPIX) sGT[tid] = gp.GT[tid];
    __syncthreads();

    const int lane = tid & 31;
    const int warp = tid >> 5;
    const int gwarp = blockIdx.x * NWARPS + warp;
    const bool hasB = lane < 17;
    const int base4 = 4 * lane;
    const int baseByte = 16 * lane;

    const int ntask = (gwarp < NTASKS - 2 * WTOT) ? 3 : 2;
    const int ng = 4 * ntask;            // groups of 2 joints

    const unsigned sHbase =
        (unsigned)__cvta_generic_to_shared(&sH[warp * (SLOTS * 2 * NPIX)]);
    const float* sHw = &sH[warp * (SLOTS * 2 * NPIX)];

    // ---- per-lane pair geometry ----
    int ybO[4], xbO[4];
    {
        #pragma unroll
        for (int p = 0; p < 4; ++p) {
            int e0 = (p < 2) ? (base4 + 2 * p) : (128 + base4 + 2 * (p - 2));
            if (p >= 2 && !hasB) e0 = 0;
            int y = e0 / COL;
            ybO[p] = y * 4;
            xbO[p] = (e0 - y * COL) * 4;
        }
    }

    auto group_joint0 = [&](int gg) {
        const int task = gg >> 2;
        return (gwarp + task * WTOT) * 8 + (gg & 3) * 2;
    };

    auto issue = [&](int gg, int slot) {
        const int j0 = group_joint0(gg);
        #pragma unroll
        for (int i = 0; i < 2; ++i) {
            const int joint = j0 + i;
            const int b2 = joint / NJ;
            const int j2 = joint - b2 * NJ;
            const char* hb = reinterpret_cast<const char*>(
                outp + ((size_t)b2 * (3 * NJ) + j2) * NPIX);
            const unsigned dst = sHbase + (slot * 2 + i) * (NPIX * 4);
            CP_ASYNC16(dst + baseByte, hb + baseByte);
            if (hasB) CP_ASYNC16(dst + 512 + baseByte, hb + 512 + baseByte);
        }
        CP_COMMIT();
    };

    float d1 = 0.0f;

    auto compute = [&](int gg, int slot) {
        const int j0 = group_joint0(gg);
        const int bslot = (gg >> 2) * 8 + (gg & 3) * 2;
        const float4 tv = *reinterpret_cast<const float4*>(t + 2 * (size_t)j0);
        const float4 vv = *reinterpret_cast<const float4*>(v + 2 * (size_t)j0);
        #pragma unroll
        for (int i = 0; i < 2; ++i) {
            const float* sj = sHw + (slot * 2 + i) * NPIX;
            const float4 a = *reinterpret_cast<const float4*>(sj + base4);
            float4 b = make_float4(0.0f, 0.0f, 0.0f, 0.0f);
            if (hasB) b = *reinterpret_cast<const float4*>(sj + 128 + base4);

            const unsigned long long p01 = pack2(a.x, a.y);
            const unsigned long long p23 = pack2(a.z, a.w);
            const unsigned long long p45 = pack2(b.x, b.y);
            const unsigned long long p67 = pack2(b.z, b.w);

            unsigned long long s2 = fma2(p01, p01, mul2(p23, p23));
            s2 = fma2(p45, p45, s2);
            s2 = fma2(p67, p67, s2);
            float h2lo, h2hi; unpack2(s2, h2lo, h2hi);
            const float ph2 = h2lo + h2hi;

            const float t0 = i ? tv.z : tv.x;
            const float t1 = i ? tv.w : tv.y;
            const float v0 = i ? vv.z : vv.x;
            const int xi = (int)(t0 * 14.0f);
            const int yi = (int)(t1 * 14.0f);
            const bool inb = (xi >= 0) && (xi <= COL - 1) && (yi >= 0) && (yi <= COL - 1);
            const bool vis = ((int)v0) == 1;
            const bool scat = vis && inb;       // warp-uniform

            if (scat) {
                unsigned long long sh = add2(add2(p01, p23), add2(p45, p67));
                float shlo, shhi; unpack2(sh, shlo, shhi);
                const float ph = shlo + shhi;

                const char* gyrowB = reinterpret_cast<const char*>(sGT + yi * COL);
                const char* gxrowB = reinterpret_cast<const char*>(sGT + xi * COL);
                unsigned long long acc = 0ull;
                {
                    const float gy = *(const float*)(gyrowB + ybO[0]);
                    const unsigned long long gx2 = *(const unsigned long long*)(gxrowB + xbO[0]);
                    acc = fma2(mul2(gx2, p01), pack2(gy, gy), acc);
                }
                {
                    const float gy = *(const float*)(gyrowB + ybO[1]);
                    const unsigned long long gx2 = *(const unsigned long long*)(gxrowB + xbO[1]);
                    acc = fma2(mul2(gx2, p23), pack2(gy, gy), acc);
                }
                {
                    const float gy = *(const float*)(gyrowB + ybO[2]);
                    const unsigned long long gx2 = *(const unsigned long long*)(gxrowB + xbO[2]);
                    acc = fma2(mul2(gx2, p45), pack2(gy, gy), acc);
                }
                {
                    const float gy = *(const float*)(gyrowB + ybO[3]);
                    const unsigned long long gx2 = *(const unsigned long long*)(gxrowB + xbO[3]);
                    acc = fma2(mul2(gx2, p67), pack2(gy, gy), acc);
                }
                float htlo, hthi; unpack2(acc, htlo, hthi);
                const float phtt = htlo + hthi;

                const float4 lut = gp.lut[yi * COL + xi];   // single LDC.128

                d1 += fmaf(lut.x, phtt, fmaf(lut.y, ph, ph2));
                if (lane == 0) d1 += lut.z;

                float best = fmaxf(fmaxf(a.x, a.y), fmaxf(a.z, a.w));
                if (hasB) best = fmaxf(best, fmaxf(fmaxf(b.x, b.y), fmaxf(b.z, b.w)));
                int idx = 0x7fffffff;
                if (hasB) {
                    idx = (b.w == best) ? (131 + base4) : idx;
                    idx = (b.z == best) ? (130 + base4) : idx;
                    idx = (b.y == best) ? (129 + base4) : idx;
                    idx = (b.x == best) ? (128 + base4) : idx;
                }
                idx = (a.w == best) ? (3 + base4) : idx;
                idx = (a.z == best) ? (2 + base4) : idx;
                idx = (a.y == best) ? (1 + base4) : idx;
                idx = (a.x == best) ? (base4) : idx;

                unsigned u = __float_as_uint(best);
                unsigned mono = ((int)u < 0) ? ~u : (u | 0x80000000u);
                unsigned mmax = __reduce_max_sync(0xffffffffu, mono);
                int cand = (mono == mmax) ? idx : 0x7fffffff;
                int bidx = __reduce_min_sync(0xffffffffu, cand);
                if (lane == 0) sBidx[warp][bslot + i] = bidx;
            } else {
                float pr = 0.0f;
                if (lane < 4) {
                    pr = fmaf(a.x, a.x, a.y * a.y);
                    if (lane < 3) pr += fmaf(a.z, a.z, a.w * a.w);
                }
                d1 += ph2 - pr;
            }
        }
    };

    // ---- continuous 3-slot pipeline over all ng groups ----
    issue(0, 0); issue(1, 1); issue(2, 2);
    {
        int slot = 0;
        for (int gg = 0; gg + 3 < ng; ++gg) {
            CP_WAIT(2);
            compute(gg, slot);
            issue(gg + 3, slot);
            slot = (slot == 2) ? 0 : slot + 1;
        }
        CP_WAIT(2); compute(ng - 3, slot); slot = (slot == 2) ? 0 : slot + 1;
        CP_WAIT(1); compute(ng - 2, slot); slot = (slot == 2) ? 0 : slot + 1;
        CP_WAIT(0); compute(ng - 1, slot);
    }

    // warp-reduce d1
    #pragma unroll
    for (int off = 16; off; off >>= 1)
        d1 += __shfl_xor_sync(0xffffffffu, d1, off);

    __syncwarp();

    // ---- phase B: one joint per lane (up to 24) ----
    float d2 = 0.0f, cntf = 0.0f;
    if (lane < ntask * 8) {
        const int joint = (gwarp + (lane >> 3) * WTOT) * 8 + (lane & 7);
        const float t0 = t[2 * joint];
        const float t1 = t[2 * joint + 1];
        const float v0 = v[2 * joint];
        const int xi = (int)(t0 * 14.0f);
        const int yi = (int)(t1 * 14.0f);
        const bool inb = (xi >= 0) && (xi <= COL - 1) && (yi >= 0) && (yi <= COL - 1);
        const bool vis = ((int)v0) == 1;
        const float vef = (vis && !inb) ? 0.0f : v0;
        const float veI = (((int)vef) == 1) ? 1.0f : 0.0f;
        cntf = veI;

        if (vis && inb) {
            const int b2 = joint / NJ;
            const int j2 = joint - b2 * NJ;
            const int bidx = sBidx[warp][lane];
            const size_t ob = (size_t)b2 * (3 * NJ) * NPIX;
            const float ox = outp[ob + (size_t)(NJ + j2) * NPIX + bidx];
            const float oy = outp[ob + (size_t)(2 * NJ + j2) * NPIX + bidx];
            const int yc = bidx / COL;
            const int xc = bidx - yc * COL;
            const float px = (ox + (float)xc) * (1.0f / 14.0f);
            const float py = (oy + (float)yc) * (1.0f / 14.0f);
            const float dx = (px - t0) * vef;
            const float dy = (py - t1) * vef;
            d2 = fmaf(dx, dx, dy * dy);
        }
    }
    #pragma unroll
    for (int off = 16; off; off >>= 1) {
        d2   += __shfl_xor_sync(0xffffffffu, d2, off);
        cntf += __shfl_xor_sync(0xffffffffu, cntf, off);
    }

    if (lane == 0) { sred[warp][0] = d1; sred[warp][1] = d2; sred[warp][2] = cntf; }
    __syncthreads();

    if (tid == 0) {
        float a = 0.0f, bsum = 0.0f, c = 0.0f;
        #pragma unroll
        for (int w = 0; w < NWARPS; ++w) { a += sred[w][0]; bsum += sred[w][1]; c += sred[w][2]; }
        g_d1[blockIdx.x] = a;
        g_d2[blockIdx.x] = bsum;
        g_cnt[blockIdx.x] = c;
        __threadfence();
        unsigned old = atomicAdd(&g_ticket, 1u);
        s_last = (old == GRID - 1);
    }
    __syncthreads();

    // ---- last block: grid reduction ----
    if (s_last) {
        if (tid == 0) g_ticket = 0;          // net-zero per run
        __threadfence();
        double a = 0.0, bsum = 0.0, c = 0.0;
        for (int i = tid; i < GRID; i += THREADS) {
            a    += (double)g_d1[i];
            bsum += (double)g_d2[i];
            c    += (double)g_cnt[i];
        }
        #pragma unroll
        for (int off = 16; off; off >>= 1) {
            a    += __shfl_xor_sync(0xffffffffu, a, off);
            bsum += __shfl_xor_sync(0xffffffffu, bsum, off);
            c    += __shfl_xor_sync(0xffffffffu, c, off);
        }
        if (lane == 0) { dra[warp] = a; drb[warp] = bsum; drc[warp] = c; }
        __syncthreads();
        if (tid == 0) {
            double A = 0.0, B = 0.0, C = 0.0;
            #pragma unroll
            for (int w = 0; w < NWARPS; ++w) { A += dra[w]; B += drb[w]; C += drc[w]; }
            o[0] = (float)(A / C + B / C);   // n2 == cnt (v is a tiled 0/1 mask)
        }
    }
}

extern "C" void kernel_launch(void* const* d_in, const int* in_sizes, int n_in,
                              void* d_out, int out_size)
{
    const float* outp = (const float*)d_in[0];
    const float* t    = (const float*)d_in[1];
    const float* v    = (const float*)d_in[2];

    GParams gp;
    {
        double w[9], ws = 0.0;
        for (int k = 0; k < 9; ++k) { w[k] = exp(-0.5 * (double)((k - 4) * (k - 4))); ws += w[k]; }
        for (int k = 0; k < 9; ++k) w[k] /= ws;
        for (int r = 0; r < COL; ++r)
            for (int c = 0; c < COL; ++c) {
                double s = 0.0;
                for (int k = 0; k < 9; ++k) {
                    int rr = r + k;   // padded row, pad=4, 'symmetric'
                    int m = (rr < 4) ? (3 - rr) : ((rr > 17) ? (31 - rr) : (rr - 4));
                    if (m == c) s += w[k];
                }
                gp.GT[c * COL + r] = (float)s;
            }
        float cmin[COL], cmax[COL];
        for (int c = 0; c < COL; ++c) {
            float mn = 1e30f, mx = -1e30f;
            for (int r = 0; r < COL; ++r) {
                float gv = gp.GT[c * COL + r];
                mn = fminf(mn, gv);
                mx = fmaxf(mx, gv);
            }
            cmin[c] = mn;
            cmax[c] = mx;
        }
        for (int yic = 0; yic < COL; ++yic)
            for (int xic = 0; xic < COL; ++xic) {
                float mn = cmin[yic] * cmin[xic];
                float mx = cmax[yic] * cmax[xic];
                double invd = 1.0 / ((double)mx - (double)mn);
                float inv = (float)invd;
                double s = 0.0;
                for (int y = 0; y < COL; ++y)
                    for (int x = 0; x < COL; ++x) {
                        float tt = gp.GT[yic * COL + y] * gp.GT[xic * COL + x];
                        float ttn = (tt - mn) * inv;
                        s += (double)ttn * (double)ttn;
                    }
                const int cell = yic * COL + xic;
                gp.lut[cell].x = -2.0f * inv;              // m2inv
                gp.lut[cell].y = -2.0f * (-mn * inv);      // m2nmi
                gp.lut[cell].z = (float)s;                 // T2
                gp.lut[cell].w = 0.0f;
            }
    }

    main_kernel<<<GRID, THREADS>>>(outp, t, v, (float*)d_out, gp);
}